// round 7
// baseline (speedup 1.0000x reference)
#include <cuda_runtime.h>
#include <math.h>
#include <stdint.h>

// Problem constants
#define Bc   4
#define Sc   1024
#define HIDc 1024
#define Hc   16
#define Dc   64

// Scratch for Q, K, V in [B,H,S,D] layout (16 MB each)
__device__ float g_q[Bc * Hc * Sc * Dc];
__device__ float g_k[Bc * Hc * Sc * Dc];
__device__ float g_v[Bc * Hc * Sc * Dc];

__device__ __forceinline__ uint32_t fu(float x) { return __float_as_uint(x); }

// m16n8k8 TF32 mma.sync (base-arch PTX; HMMA on Blackwell)
__device__ __forceinline__ void mma8(float* c, const uint32_t* a, const uint32_t* b) {
    asm volatile(
        "mma.sync.aligned.m16n8k8.row.col.f32.tf32.tf32.f32 "
        "{%0,%1,%2,%3}, {%4,%5,%6,%7}, {%8,%9}, {%0,%1,%2,%3};"
        : "+f"(c[0]), "+f"(c[1]), "+f"(c[2]), "+f"(c[3])
        : "r"(a[0]), "r"(a[1]), "r"(a[2]), "r"(a[3]), "r"(b[0]), "r"(b[1]));
}

__device__ __forceinline__ void split4(float4 v, float4& hi, float4& lo) {
    hi.x = __uint_as_float(__float_as_uint(v.x) & 0xFFFFE000u); lo.x = v.x - hi.x;
    hi.y = __uint_as_float(__float_as_uint(v.y) & 0xFFFFE000u); lo.y = v.y - hi.y;
    hi.z = __uint_as_float(__float_as_uint(v.z) & 0xFFFFE000u); lo.z = v.z - hi.z;
    hi.w = __uint_as_float(__float_as_uint(v.w) & 0xFFFFE000u); lo.w = v.w - hi.w;
}

// ---------------------------------------------------------------------------
// Projection GEMM via mma.sync TF32 3x-split.
// C[4096,1024] = X @ W + bias, scattered to [B,H,S,D].
// Block: 128x128 tile, k-chunks of 32, 256 threads (8 warps a 64x32).
// ---------------------------------------------------------------------------
#define AHI 0        // 128 x 36
#define ALO 4608     // 128 x 36
#define BHI 9216     // 32 x 136
#define BLO 13568    // 32 x 136
#define GEMM_SMEMF 17920
#define GEMM_SMEM_BYTES (GEMM_SMEMF * 4)   // 71680

__global__ __launch_bounds__(256, 2)
void gemm_mma(const float* __restrict__ X,
              const float* __restrict__ Wq, const float* __restrict__ bq,
              const float* __restrict__ Wk, const float* __restrict__ bk,
              const float* __restrict__ Wv, const float* __restrict__ bv)
{
    extern __shared__ float sm[];
    const int tid  = threadIdx.x;
    const int wid  = tid >> 5;
    const int lane = tid & 31;
    const int g_   = lane >> 2;      // group id 0..7
    const int t_   = lane & 3;       // thread-in-group 0..3
    const int z    = blockIdx.z;
    const int n0   = blockIdx.x * 128;
    const int m0   = blockIdx.y * 128;
    const int warp_m = (wid & 1) * 64;
    const int warp_n = (wid >> 1) * 32;

    const float* W    = (z == 0) ? Wq : (z == 1) ? Wk : Wv;
    const float* bias = (z == 0) ? bq : (z == 1) ? bk : bv;
    float*       outp = (z == 0) ? g_q : (z == 1) ? g_k : g_v;

    float acc[4][4][4];
#pragma unroll
    for (int i = 0; i < 4; i++)
#pragma unroll
        for (int j = 0; j < 4; j++)
#pragma unroll
            for (int r = 0; r < 4; r++) acc[i][j][r] = 0.f;

    for (int c = 0; c < 32; c++) {
        const int k0c = c * 32;
        // Load + split A chunk: X[m0..+128, k0c..+32] -> AHI/ALO (pitch 36)
#pragma unroll
        for (int i = 0; i < 4; i++) {
            int f  = tid + i * 256;
            int r  = f >> 3;
            int c4 = (f & 7) << 2;
            float4 v = *(const float4*)(X + (size_t)(m0 + r) * HIDc + k0c + c4);
            float4 hi, lo;
            split4(v, hi, lo);
            *(float4*)&sm[AHI + r * 36 + c4] = hi;
            *(float4*)&sm[ALO + r * 36 + c4] = lo;
        }
        // Load + split B chunk: W[k0c..+32, n0..+128] -> BHI/BLO (pitch 136)
#pragma unroll
        for (int i = 0; i < 4; i++) {
            int f  = tid + i * 256;
            int r  = f >> 5;
            int nc = (f & 31) << 2;
            float4 v = *(const float4*)(W + (size_t)(k0c + r) * HIDc + n0 + nc);
            float4 hi, lo;
            split4(v, hi, lo);
            *(float4*)&sm[BHI + r * 136 + nc] = hi;
            *(float4*)&sm[BLO + r * 136 + nc] = lo;
        }
        __syncthreads();

#pragma unroll
        for (int ks = 0; ks < 4; ks++) {
            // B fragments: col n = g_, rows k = ks*8 + t_ (+4)
            uint32_t bh[4][2], bl[4][2];
#pragma unroll
            for (int jt = 0; jt < 4; jt++) {
                int nn = warp_n + jt * 8 + g_;
                int kr = ks * 8 + t_;
                bh[jt][0] = fu(sm[BHI + kr * 136 + nn]);
                bh[jt][1] = fu(sm[BHI + (kr + 4) * 136 + nn]);
                bl[jt][0] = fu(sm[BLO + kr * 136 + nn]);
                bl[jt][1] = fu(sm[BLO + (kr + 4) * 136 + nn]);
            }
#pragma unroll
            for (int it = 0; it < 4; it++) {
                int rr = warp_m + it * 16 + g_;
                int kk = ks * 8 + t_;
                uint32_t ah[4], al[4];
                ah[0] = fu(sm[AHI + rr * 36 + kk]);
                ah[1] = fu(sm[AHI + (rr + 8) * 36 + kk]);
                ah[2] = fu(sm[AHI + rr * 36 + kk + 4]);
                ah[3] = fu(sm[AHI + (rr + 8) * 36 + kk + 4]);
                al[0] = fu(sm[ALO + rr * 36 + kk]);
                al[1] = fu(sm[ALO + (rr + 8) * 36 + kk]);
                al[2] = fu(sm[ALO + rr * 36 + kk + 4]);
                al[3] = fu(sm[ALO + (rr + 8) * 36 + kk + 4]);
#pragma unroll
                for (int jt = 0; jt < 4; jt++) {
                    mma8(acc[it][jt], ah, bh[jt]);
                    mma8(acc[it][jt], ah, bl[jt]);
                    mma8(acc[it][jt], al, bh[jt]);
                }
            }
        }
        __syncthreads();
    }

    // Epilogue: c0=(g,2t) c1=(g,2t+1) c2=(g+8,2t) c3=(g+8,2t+1); scatter + bias
#pragma unroll
    for (int it = 0; it < 4; it++) {
#pragma unroll
        for (int jt = 0; jt < 4; jt++) {
            int nn = n0 + warp_n + jt * 8 + 2 * t_;
            int h  = nn >> 6;
            int d  = nn & 63;
            float b0 = bias[nn], b1 = bias[nn + 1];
            {
                int m = m0 + warp_m + it * 16 + g_;
                int bb = m >> 10, s = m & 1023;
                float2 o = make_float2(acc[it][jt][0] + b0, acc[it][jt][1] + b1);
                *(float2*)&outp[(((size_t)(bb * Hc + h)) * Sc + s) * Dc + d] = o;
            }
            {
                int m = m0 + warp_m + it * 16 + g_ + 8;
                int bb = m >> 10, s = m & 1023;
                float2 o = make_float2(acc[it][jt][2] + b0, acc[it][jt][3] + b1);
                *(float2*)&outp[(((size_t)(bb * Hc + h)) * Sc + s) * Dc + d] = o;
            }
        }
    }
}

// ---------------------------------------------------------------------------
// Kernel B: fused attention (R2 version — 64x64 tiles, 4x4 micro, 256 thr)
// ---------------------------------------------------------------------------
#define QOFF  0                     // 64 x 65
#define KOFF  4160                  // 64 x 65
#define VOFF  8320                  // 64 x 68
#define EOFF  12672                 // 127 x 65
#define POFF  20927                 // 64 x 65
#define DNOFF 25087                 // 64
#define SKOFF 25151                 // 64
#define AMOFF 25215                 // 64
#define SMEMF 25280
#define ATTN_SMEM_BYTES (SMEMF * 4) // 101120 B

__global__ __launch_bounds__(256) void attn_kernel(const float* __restrict__ attn_mask,
                                                   const int*   __restrict__ skim,
                                                   const float* __restrict__ dist_emb,
                                                   float*       __restrict__ out)
{
    extern __shared__ float smf[];
    const int tid = threadIdx.x;
    const int l0  = blockIdx.x * 64;
    const int bh  = blockIdx.y;
    const int b   = bh >> 4;
    const int h   = bh & 15;
    const int ty  = tid >> 4;
    const int tx  = tid & 15;

    const float* q = g_q + (size_t)bh * Sc * Dc;
    const float* k = g_k + (size_t)bh * Sc * Dc;
    const float* v = g_v + (size_t)bh * Sc * Dc;

#pragma unroll
    for (int i = 0; i < 4; i++) {
        int f   = tid + i * 256;
        int row = f >> 4;
        int c4  = (f & 15) << 2;
        float4 val = *(const float4*)(q + (size_t)(l0 + row) * 64 + c4);
        smf[QOFF + row * 65 + c4 + 0] = val.x;
        smf[QOFF + row * 65 + c4 + 1] = val.y;
        smf[QOFF + row * 65 + c4 + 2] = val.z;
        smf[QOFF + row * 65 + c4 + 3] = val.w;
    }
    if (tid < 64) smf[DNOFF + tid] = 0.f;

    float acc[4][4];
#pragma unroll
    for (int i = 0; i < 4; i++)
#pragma unroll
        for (int j = 0; j < 4; j++) acc[i][j] = 0.f;

    for (int r0 = 0; r0 < Sc; r0 += 64) {
        __syncthreads();

#pragma unroll
        for (int i = 0; i < 4; i++) {
            int f   = tid + i * 256;
            int row = f >> 4;
            int c4  = (f & 15) << 2;
            float4 kv = *(const float4*)(k + (size_t)(r0 + row) * 64 + c4);
            smf[KOFF + row * 65 + c4 + 0] = kv.x;
            smf[KOFF + row * 65 + c4 + 1] = kv.y;
            smf[KOFF + row * 65 + c4 + 2] = kv.z;
            smf[KOFF + row * 65 + c4 + 3] = kv.w;
            float4 vv = *(const float4*)(v + (size_t)(r0 + row) * 64 + c4);
            *(float4*)&smf[VOFF + row * 68 + c4] = vv;
        }
        {
            int ebase = l0 - r0 + 960;
#pragma unroll
            for (int i = 0; i < 8; i++) {
                int f = tid + i * 256;
                if (f < 2032) {
                    int row = f >> 4;
                    int c4  = (f & 15) << 2;
                    float4 ev = *(const float4*)(dist_emb + (size_t)(ebase + row) * 64 + c4);
                    smf[EOFF + row * 65 + c4 + 0] = ev.x;
                    smf[EOFF + row * 65 + c4 + 1] = ev.y;
                    smf[EOFF + row * 65 + c4 + 2] = ev.z;
                    smf[EOFF + row * 65 + c4 + 3] = ev.w;
                }
            }
        }
        if (tid < 64) {
            smf[AMOFF + tid] = attn_mask[b * Sc + r0 + tid];
            smf[SKOFF + tid] = (float)skim[b * Sc + r0 + tid];
        }
        __syncthreads();

        float s4[4][4];
#pragma unroll
        for (int i = 0; i < 4; i++)
#pragma unroll
            for (int j = 0; j < 4; j++) s4[i][j] = 0.f;

        const int   jb   = ((ty - tx) << 2) + 63;
        const float* Qrow = &smf[QOFF + (ty * 4) * 65];
        const float* Krow = &smf[KOFF + (tx * 4) * 65];
        const float* Erow = &smf[EOFF + (jb - 3) * 65];

#pragma unroll 4
        for (int d = 0; d < 64; d++) {
            float qv[4], kv[4], ev[7];
#pragma unroll
            for (int i = 0; i < 4; i++) qv[i] = Qrow[i * 65 + d];
#pragma unroll
            for (int i = 0; i < 4; i++) kv[i] = Krow[i * 65 + d];
#pragma unroll
            for (int t = 0; t < 7; t++) ev[t] = Erow[t * 65 + d];
#pragma unroll
            for (int il = 0; il < 4; il++)
#pragma unroll
                for (int ir = 0; ir < 4; ir++)
                    s4[il][ir] += qv[il] * (kv[ir] + ev[il - ir + 3]);
        }

        float rowsum[4];
#pragma unroll
        for (int il = 0; il < 4; il++) {
            rowsum[il] = 0.f;
#pragma unroll
            for (int ir = 0; ir < 4; ir++) {
                float p = __expf(s4[il][ir] * 0.125f + smf[AMOFF + tx * 4 + ir])
                          * smf[SKOFF + tx * 4 + ir];
                smf[POFF + (ty * 4 + il) * 65 + tx * 4 + ir] = p;
                rowsum[il] += p;
            }
        }
#pragma unroll
        for (int il = 0; il < 4; il++) {
            float rs = rowsum[il];
            rs += __shfl_xor_sync(0xffffffffu, rs, 1);
            rs += __shfl_xor_sync(0xffffffffu, rs, 2);
            rs += __shfl_xor_sync(0xffffffffu, rs, 4);
            rs += __shfl_xor_sync(0xffffffffu, rs, 8);
            if (tx == 0) smf[DNOFF + ty * 4 + il] += rs;
        }
        __syncthreads();

        const float* Prow = &smf[POFF + (ty * 4) * 65];
#pragma unroll 4
        for (int rr = 0; rr < 64; rr++) {
            float pv[4];
#pragma unroll
            for (int il = 0; il < 4; il++) pv[il] = Prow[il * 65 + rr];
            float4 vv = *(const float4*)&smf[VOFF + rr * 68 + tx * 4];
            float vvr[4] = {vv.x, vv.y, vv.z, vv.w};
#pragma unroll
            for (int il = 0; il < 4; il++)
#pragma unroll
                for (int id = 0; id < 4; id++)
                    acc[il][id] += pv[il] * vvr[id];
        }
    }
    __syncthreads();

#pragma unroll
    for (int il = 0; il < 4; il++) {
        int l = l0 + ty * 4 + il;
        float dinv = 1.f / (1e-8f + smf[DNOFF + ty * 4 + il]);
#pragma unroll
        for (int id = 0; id < 4; id++) {
            out[((size_t)(b * Sc + l)) * HIDc + h * 64 + tx * 4 + id] =
                acc[il][id] * dinv;
        }
    }
}

// ---------------------------------------------------------------------------
extern "C" void kernel_launch(void* const* d_in, const int* in_sizes, int n_in,
                              void* d_out, int out_size)
{
    const float* hidden = (const float*)d_in[0];
    const float* amask  = (const float*)d_in[1];
    const int*   skim   = (const int*)  d_in[2];
    const float* Wq     = (const float*)d_in[3];
    const float* bq     = (const float*)d_in[4];
    const float* Wk     = (const float*)d_in[5];
    const float* bk     = (const float*)d_in[6];
    const float* Wv     = (const float*)d_in[7];
    const float* bv     = (const float*)d_in[8];
    const float* demb   = (const float*)d_in[9];
    float* out = (float*)d_out;

    cudaFuncSetAttribute(gemm_mma, cudaFuncAttributeMaxDynamicSharedMemorySize,
                         GEMM_SMEM_BYTES);
    dim3 ggrid(HIDc / 128, (Bc * Sc) / 128, 3);   // (8, 32, 3)
    gemm_mma<<<ggrid, 256, GEMM_SMEM_BYTES>>>(hidden, Wq, bq, Wk, bk, Wv, bv);

    cudaFuncSetAttribute(attn_kernel, cudaFuncAttributeMaxDynamicSharedMemorySize,
                         ATTN_SMEM_BYTES);
    dim3 agrid(Sc / 64, Bc * Hc);
    attn_kernel<<<agrid, 256, ATTN_SMEM_BYTES>>>(amask, skim, demb, out);
}

// round 8
// speedup vs baseline: 1.4989x; 1.4989x over previous
#include <cuda_runtime.h>
#include <math.h>

// Problem constants
#define Bc   4
#define Sc   1024
#define HIDc 1024
#define Hc   16
#define Dc   64

// Scratch for Q, K, V in [B,H,S,D] layout (16 MB each)
__device__ float g_q[Bc * Hc * Sc * Dc];
__device__ float g_k[Bc * Hc * Sc * Dc];
__device__ float g_v[Bc * Hc * Sc * Dc];

// ---------------------------------------------------------------------------
// Kernel A: projection GEMM  C = X @ W + bias, scattered to [B,H,S,D]
// (proven R2 scalar version, ~660us for all three — at the FFMA roofline)
// ---------------------------------------------------------------------------
__global__ __launch_bounds__(256) void gemm_proj(const float* __restrict__ X,
                                                 const float* __restrict__ W,
                                                 const float* __restrict__ bias,
                                                 int which)
{
    __shared__ float As[16][132];   // transposed A tile: As[k][m]
    __shared__ float Bs[16][132];   // Bs[k][n]
    float* outp = (which == 0) ? g_q : (which == 1) ? g_k : g_v;

    const int tid = threadIdx.x;
    const int m0  = blockIdx.y * 128;
    const int n0  = blockIdx.x * 128;
    const int ty  = tid >> 4;     // 0..15
    const int tx  = tid & 15;     // 0..15

    float acc[8][8];
#pragma unroll
    for (int i = 0; i < 8; i++)
#pragma unroll
        for (int j = 0; j < 8; j++) acc[i][j] = 0.f;

    for (int k0 = 0; k0 < 1024; k0 += 16) {
#pragma unroll
        for (int i = 0; i < 2; i++) {
            int f   = tid + i * 256;          // 0..511 float4s
            int row = f >> 2;
            int kc  = (f & 3) << 2;
            float4 va = *(const float4*)(X + (size_t)(m0 + row) * 1024 + k0 + kc);
            As[kc + 0][row] = va.x;
            As[kc + 1][row] = va.y;
            As[kc + 2][row] = va.z;
            As[kc + 3][row] = va.w;
        }
#pragma unroll
        for (int i = 0; i < 2; i++) {
            int f  = tid + i * 256;
            int kr = f >> 5;
            int nc = (f & 31) << 2;
            *(float4*)&Bs[kr][nc] =
                *(const float4*)(W + (size_t)(k0 + kr) * 1024 + n0 + nc);
        }
        __syncthreads();

#pragma unroll
        for (int kk = 0; kk < 16; kk++) {
            float a[8], b[8];
            *(float4*)&a[0] = *(const float4*)&As[kk][ty * 8];
            *(float4*)&a[4] = *(const float4*)&As[kk][ty * 8 + 4];
            *(float4*)&b[0] = *(const float4*)&Bs[kk][tx * 8];
            *(float4*)&b[4] = *(const float4*)&Bs[kk][tx * 8 + 4];
#pragma unroll
            for (int i = 0; i < 8; i++)
#pragma unroll
                for (int j = 0; j < 8; j++)
                    acc[i][j] += a[i] * b[j];
        }
        __syncthreads();
    }

#pragma unroll
    for (int i = 0; i < 8; i++) {
        int m = m0 + ty * 8 + i;
        int b = m >> 10;
        int s = m & 1023;
#pragma unroll
        for (int j = 0; j < 8; j++) {
            int n = n0 + tx * 8 + j;
            int h = n >> 6;
            int d = n & 63;
            outp[(((size_t)(b * Hc + h)) * Sc + s) * Dc + d] = acc[i][j] + bias[n];
        }
    }
}

// ---------------------------------------------------------------------------
// Kernel B: fused attention, 64x64 tiles, 4x4 micro, 256 threads.
// K and E rows stored with bank rotation  addr = base + r*65 + (r>>5)
// -> conflict-free lane-spread loads (was 2-3-way conflicted).
// ---------------------------------------------------------------------------
#define QOFF  0                     // 64 x 65
#define KOFF  4160                  // 64 x 65 + 2 swizzle pad
#define VOFF  8324                  // 64 x 68
#define EOFF  12676                 // 127 x 65 + 4 swizzle pad
#define POFF  20936                 // 64 x 65
#define DNOFF 25096                 // 64
#define SKOFF 25160                 // 64
#define AMOFF 25224                 // 64
#define SMEMF 25288
#define ATTN_SMEM_BYTES (SMEMF * 4) // 101152 B

__global__ __launch_bounds__(256) void attn_kernel(const float* __restrict__ attn_mask,
                                                   const int*   __restrict__ skim,
                                                   const float* __restrict__ dist_emb,
                                                   float*       __restrict__ out)
{
    extern __shared__ float smf[];
    const int tid = threadIdx.x;
    const int l0  = blockIdx.x * 64;
    const int bh  = blockIdx.y;
    const int b   = bh >> 4;
    const int h   = bh & 15;
    const int ty  = tid >> 4;
    const int tx  = tid & 15;

    const float* q = g_q + (size_t)bh * Sc * Dc;
    const float* k = g_k + (size_t)bh * Sc * Dc;
    const float* v = g_v + (size_t)bh * Sc * Dc;

    // Load Q tile (64x64)
#pragma unroll
    for (int i = 0; i < 4; i++) {
        int f   = tid + i * 256;
        int row = f >> 4;
        int c4  = (f & 15) << 2;
        float4 val = *(const float4*)(q + (size_t)(l0 + row) * 64 + c4);
        smf[QOFF + row * 65 + c4 + 0] = val.x;
        smf[QOFF + row * 65 + c4 + 1] = val.y;
        smf[QOFF + row * 65 + c4 + 2] = val.z;
        smf[QOFF + row * 65 + c4 + 3] = val.w;
    }
    if (tid < 64) smf[DNOFF + tid] = 0.f;

    float acc[4][4];
#pragma unroll
    for (int i = 0; i < 4; i++)
#pragma unroll
        for (int j = 0; j < 4; j++) acc[i][j] = 0.f;

    // Hoisted swizzled base addresses (chunk-invariant)
    const int jb = ((ty - tx) << 2) + 63;      // diag row at il=ir=0
    int ebt[7];
#pragma unroll
    for (int t = 0; t < 7; t++) {
        int r = jb - 3 + t;                    // in [0,126]
        ebt[t] = EOFF + r * 65 + (r >> 5);
    }
    const int kb  = KOFF + (tx * 4) * 65 + ((tx * 4) >> 5);
    const float* Qrow = &smf[QOFF + (ty * 4) * 65];

    for (int r0 = 0; r0 < Sc; r0 += 64) {
        __syncthreads();   // prior PV done before tiles are overwritten

        // K (swizzled rows) and V
#pragma unroll
        for (int i = 0; i < 4; i++) {
            int f   = tid + i * 256;
            int row = f >> 4;
            int c4  = (f & 15) << 2;
            float4 kv = *(const float4*)(k + (size_t)(r0 + row) * 64 + c4);
            int ka = KOFF + row * 65 + (row >> 5) + c4;
            smf[ka + 0] = kv.x;
            smf[ka + 1] = kv.y;
            smf[ka + 2] = kv.z;
            smf[ka + 3] = kv.w;
            float4 vv = *(const float4*)(v + (size_t)(r0 + row) * 64 + c4);
            *(float4*)&smf[VOFF + row * 68 + c4] = vv;
        }
        // E band: rows [l0-r0+960 .. +1086], 127 rows x 64, swizzled
        {
            int ebase = l0 - r0 + 960;
#pragma unroll
            for (int i = 0; i < 8; i++) {
                int f = tid + i * 256;
                if (f < 2032) {
                    int row = f >> 4;
                    int c4  = (f & 15) << 2;
                    float4 ev = *(const float4*)(dist_emb + (size_t)(ebase + row) * 64 + c4);
                    int ea = EOFF + row * 65 + (row >> 5) + c4;
                    smf[ea + 0] = ev.x;
                    smf[ea + 1] = ev.y;
                    smf[ea + 2] = ev.z;
                    smf[ea + 3] = ev.w;
                }
            }
        }
        if (tid < 64) {
            smf[AMOFF + tid] = attn_mask[b * Sc + r0 + tid];
            smf[SKOFF + tid] = (float)skim[b * Sc + r0 + tid];
        }
        __syncthreads();

        // ---- Scores: s[il][ir] = sum_d Q[li][d] * (K[ri][d] + E[li-ri+63][d])
        float s4[4][4];
#pragma unroll
        for (int i = 0; i < 4; i++)
#pragma unroll
            for (int j = 0; j < 4; j++) s4[i][j] = 0.f;

#pragma unroll 4
        for (int d = 0; d < 64; d++) {
            float qv[4], kv[4], ev[7];
#pragma unroll
            for (int i = 0; i < 4; i++) qv[i] = Qrow[i * 65 + d];
#pragma unroll
            for (int i = 0; i < 4; i++) kv[i] = smf[kb + i * 65 + d];
#pragma unroll
            for (int t = 0; t < 7; t++) ev[t] = smf[ebt[t] + d];
#pragma unroll
            for (int il = 0; il < 4; il++)
#pragma unroll
                for (int ir = 0; ir < 4; ir++)
                    s4[il][ir] += qv[il] * (kv[ir] + ev[il - ir + 3]);
        }

        // ---- probs = exp(s/8 + attn_mask) * skim_mask ; accumulate denoms
        float rowsum[4];
#pragma unroll
        for (int il = 0; il < 4; il++) {
            rowsum[il] = 0.f;
#pragma unroll
            for (int ir = 0; ir < 4; ir++) {
                float p = __expf(s4[il][ir] * 0.125f + smf[AMOFF + tx * 4 + ir])
                          * smf[SKOFF + tx * 4 + ir];
                smf[POFF + (ty * 4 + il) * 65 + tx * 4 + ir] = p;
                rowsum[il] += p;
            }
        }
#pragma unroll
        for (int il = 0; il < 4; il++) {
            float rs = rowsum[il];
            rs += __shfl_xor_sync(0xffffffffu, rs, 1);
            rs += __shfl_xor_sync(0xffffffffu, rs, 2);
            rs += __shfl_xor_sync(0xffffffffu, rs, 4);
            rs += __shfl_xor_sync(0xffffffffu, rs, 8);
            if (tx == 0) smf[DNOFF + ty * 4 + il] += rs;
        }
        __syncthreads();

        // ---- PV accumulate: acc[li][dd] += sum_rr P[li][rr] * V[rr][dd]
        const float* Prow = &smf[POFF + (ty * 4) * 65];
#pragma unroll 4
        for (int rr = 0; rr < 64; rr++) {
            float pv[4];
#pragma unroll
            for (int il = 0; il < 4; il++) pv[il] = Prow[il * 65 + rr];
            float4 vv = *(const float4*)&smf[VOFF + rr * 68 + tx * 4];
            float vvr[4] = {vv.x, vv.y, vv.z, vv.w};
#pragma unroll
            for (int il = 0; il < 4; il++)
#pragma unroll
                for (int id = 0; id < 4; id++)
                    acc[il][id] += pv[il] * vvr[id];
        }
    }
    __syncthreads();

    // ---- write out: out[b, l, h*64 + d] = acc / (eps + denom)
#pragma unroll
    for (int il = 0; il < 4; il++) {
        int l = l0 + ty * 4 + il;
        float dinv = 1.f / (1e-8f + smf[DNOFF + ty * 4 + il]);
#pragma unroll
        for (int id = 0; id < 4; id++) {
            out[((size_t)(b * Sc + l)) * HIDc + h * 64 + tx * 4 + id] =
                acc[il][id] * dinv;
        }
    }
}

// ---------------------------------------------------------------------------
extern "C" void kernel_launch(void* const* d_in, const int* in_sizes, int n_in,
                              void* d_out, int out_size)
{
    const float* hidden = (const float*)d_in[0];
    const float* amask  = (const float*)d_in[1];
    const int*   skim   = (const int*)  d_in[2];
    const float* Wq     = (const float*)d_in[3];
    const float* bq     = (const float*)d_in[4];
    const float* Wk     = (const float*)d_in[5];
    const float* bk     = (const float*)d_in[6];
    const float* Wv     = (const float*)d_in[7];
    const float* bv     = (const float*)d_in[8];
    const float* demb   = (const float*)d_in[9];
    float* out = (float*)d_out;

    dim3 ggrid(8, 32);   // N/128, M/128
    gemm_proj<<<ggrid, 256>>>(hidden, Wq, bq, 0);
    gemm_proj<<<ggrid, 256>>>(hidden, Wk, bk, 1);
    gemm_proj<<<ggrid, 256>>>(hidden, Wv, bv, 2);

    cudaFuncSetAttribute(attn_kernel,
                         cudaFuncAttributeMaxDynamicSharedMemorySize,
                         ATTN_SMEM_BYTES);
    dim3 agrid(Sc / 64, Bc * Hc);
    attn_kernel<<<agrid, 256, ATTN_SMEM_BYTES>>>(amask, skim, demb, out);
}

// round 13
// speedup vs baseline: 1.6224x; 1.0824x over previous
#include <cuda_runtime.h>
#include <math.h>

// Problem constants
#define Bc   4
#define Sc   1024
#define HIDc 1024
#define Hc   16
#define Dc   64

// Scratch for Q, K, V in [B,H,S,D] layout (16 MB each)
__device__ float g_q[Bc * Hc * Sc * Dc];
__device__ float g_k[Bc * Hc * Sc * Dc];
__device__ float g_v[Bc * Hc * Sc * Dc];

typedef unsigned long long ull;

__device__ __forceinline__ ull pk2(float lo, float hi) {
    ull r;
    asm("mov.b64 %0, {%1, %2};" : "=l"(r) : "f"(lo), "f"(hi));
    return r;
}
__device__ __forceinline__ void upk2(float& lo, float& hi, ull v) {
    asm("mov.b64 {%0, %1}, %2;" : "=f"(lo), "=f"(hi) : "l"(v));
}
__device__ __forceinline__ void fma2(ull& d, ull a, ull b) {
    asm("fma.rn.f32x2 %0, %1, %2, %0;" : "+l"(d) : "l"(a), "l"(b));
}

// ---------------------------------------------------------------------------
// Kernel A: projection GEMM  C = X @ W + bias, scattered to [B,H,S,D]
// (proven scalar version, ~660us for all three — at the FFMA roofline)
// ---------------------------------------------------------------------------
__global__ __launch_bounds__(256) void gemm_proj(const float* __restrict__ X,
                                                 const float* __restrict__ W,
                                                 const float* __restrict__ bias,
                                                 int which)
{
    __shared__ float As[16][132];
    __shared__ float Bs[16][132];
    float* outp = (which == 0) ? g_q : (which == 1) ? g_k : g_v;

    const int tid = threadIdx.x;
    const int m0  = blockIdx.y * 128;
    const int n0  = blockIdx.x * 128;
    const int ty  = tid >> 4;
    const int tx  = tid & 15;

    float acc[8][8];
#pragma unroll
    for (int i = 0; i < 8; i++)
#pragma unroll
        for (int j = 0; j < 8; j++) acc[i][j] = 0.f;

    for (int k0 = 0; k0 < 1024; k0 += 16) {
#pragma unroll
        for (int i = 0; i < 2; i++) {
            int f   = tid + i * 256;
            int row = f >> 2;
            int kc  = (f & 3) << 2;
            float4 va = *(const float4*)(X + (size_t)(m0 + row) * 1024 + k0 + kc);
            As[kc + 0][row] = va.x;
            As[kc + 1][row] = va.y;
            As[kc + 2][row] = va.z;
            As[kc + 3][row] = va.w;
        }
#pragma unroll
        for (int i = 0; i < 2; i++) {
            int f  = tid + i * 256;
            int kr = f >> 5;
            int nc = (f & 31) << 2;
            *(float4*)&Bs[kr][nc] =
                *(const float4*)(W + (size_t)(k0 + kr) * 1024 + n0 + nc);
        }
        __syncthreads();

#pragma unroll
        for (int kk = 0; kk < 16; kk++) {
            float a[8], b[8];
            *(float4*)&a[0] = *(const float4*)&As[kk][ty * 8];
            *(float4*)&a[4] = *(const float4*)&As[kk][ty * 8 + 4];
            *(float4*)&b[0] = *(const float4*)&Bs[kk][tx * 8];
            *(float4*)&b[4] = *(const float4*)&Bs[kk][tx * 8 + 4];
#pragma unroll
            for (int i = 0; i < 8; i++)
#pragma unroll
                for (int j = 0; j < 8; j++)
                    acc[i][j] += a[i] * b[j];
        }
        __syncthreads();
    }

#pragma unroll
    for (int i = 0; i < 8; i++) {
        int m = m0 + ty * 8 + i;
        int b = m >> 10;
        int s = m & 1023;
#pragma unroll
        for (int j = 0; j < 8; j++) {
            int n = n0 + tx * 8 + j;
            int h = n >> 6;
            int d = n & 63;
            outp[(((size_t)(b * Hc + h)) * Sc + s) * Dc + d] = acc[i][j] + bias[n];
        }
    }
}

// ---------------------------------------------------------------------------
// Kernel B: fused attention. 64x64 tiles, 8x4 micro-tile, 128 threads,
// f32x2 d-pair packed score FMAs.
// K rows:  rot = 2*((r>>2)&15)  (64 rows, never wraps)
// E rows:  rot = 2*((r>>2)&31)  (127 rows, MONOTONE -> no row overlap;
//                                this fixes the R10 rows-63/64 corruption)
// ---------------------------------------------------------------------------
#define ROTK(r) ((((r) >> 2) & 15) << 1)
#define ROTE(r) ((((r) >> 2) & 31) << 1)

#define QOFF  0                     // 64 x 68                 = 4352
#define KOFF  4352                  // 64 x 68 + 32 rot        = 4384
#define VOFF  8736                  // 64 x 68                 = 4352
#define EOFF  13088                 // 127 x 68 + 64 rot       = 8700
#define POFF  21788                 // 64 x 66                 = 4224
#define DNOFF 26012                 // 64
#define AMOFF 26076                 // 64
#define SKOFF 26140                 // 64
#define SMEMF 26208
#define ATTN_SMEM_BYTES (SMEMF * 4) // 104832 B (2 CTAs/SM)

__global__ __launch_bounds__(128) void attn_kernel(const float* __restrict__ attn_mask,
                                                   const int*   __restrict__ skim,
                                                   const float* __restrict__ dist_emb,
                                                   float*       __restrict__ out)
{
    extern __shared__ float smf[];
    const int tid = threadIdx.x;
    const int l0  = blockIdx.x * 64;
    const int bh  = blockIdx.y;
    const int b   = bh >> 4;
    const int h   = bh & 15;
    const int ty  = tid >> 4;   // 0..7  -> 8 query rows each
    const int tx  = tid & 15;   // 0..15 -> 4 key cols each

    const float* q = g_q + (size_t)bh * Sc * Dc;
    const float* k = g_k + (size_t)bh * Sc * Dc;
    const float* v = g_v + (size_t)bh * Sc * Dc;

    // Load Q tile (64x64), plain stride 68
#pragma unroll
    for (int i = 0; i < 8; i++) {
        int f   = tid + i * 128;       // 0..1023 float4s
        int row = f >> 4;
        int c4  = (f & 15) << 2;
        float4 val = *(const float4*)(q + (size_t)(l0 + row) * 64 + c4);
        *(float4*)&smf[QOFF + row * 68 + c4] = val;
    }
    if (tid < 64) smf[DNOFF + tid] = 0.f;

    ull pv2[8][2];                 // PV acc: pairs along d
#pragma unroll
    for (int i = 0; i < 8; i++) { pv2[i][0] = 0ull; pv2[i][1] = 0ull; }

    // Hoisted base addresses (chunk-invariant)
    const int jb0 = ty * 8 - tx * 4 + 60;      // in [0,116]
    int ebt[11];
#pragma unroll
    for (int t = 0; t < 11; t++) {
        int r = jb0 + t;                        // in [0,126]
        ebt[t] = EOFF + r * 68 + ROTE(r);
    }
    const int qb = QOFF + ty * 8 * 68;
    const int kb = KOFF + tx * 4 * 68 + (tx << 1);   // ROTK(4*tx) = 2*tx

    for (int r0 = 0; r0 < Sc; r0 += 64) {
        __syncthreads();   // prior PV done before tiles are overwritten

        // K (rotated rows, float2 stores) and V (plain float4)
#pragma unroll
        for (int i = 0; i < 8; i++) {
            int f   = tid + i * 128;
            int row = f >> 4;
            int c4  = (f & 15) << 2;
            float4 kv = *(const float4*)(k + (size_t)(r0 + row) * 64 + c4);
            int ka = KOFF + row * 68 + ROTK(row) + c4;
            *(float2*)&smf[ka]     = make_float2(kv.x, kv.y);
            *(float2*)&smf[ka + 2] = make_float2(kv.z, kv.w);
            float4 vv = *(const float4*)(v + (size_t)(r0 + row) * 64 + c4);
            *(float4*)&smf[VOFF + row * 68 + c4] = vv;
        }
        // E band: rows [l0-r0+960 .. +1086], 127 rows x 64, monotone rotation
        {
            int ebase = l0 - r0 + 960;
#pragma unroll
            for (int i = 0; i < 16; i++) {
                int f = tid + i * 128;
                if (f < 2032) {
                    int row = f >> 4;
                    int c4  = (f & 15) << 2;
                    float4 ev = *(const float4*)(dist_emb + (size_t)(ebase + row) * 64 + c4);
                    int ea = EOFF + row * 68 + ROTE(row) + c4;
                    *(float2*)&smf[ea]     = make_float2(ev.x, ev.y);
                    *(float2*)&smf[ea + 2] = make_float2(ev.z, ev.w);
                }
            }
        }
        if (tid < 64) {
            smf[AMOFF + tid] = attn_mask[b * Sc + r0 + tid];
            smf[SKOFF + tid] = (float)skim[b * Sc + r0 + tid];
        }
        __syncthreads();

        // ---- Scores: s[il][ir] = sum_d q*(k) + q*(e), f32x2 over d-pairs
        ull s2[8][4];
#pragma unroll
        for (int i = 0; i < 8; i++)
#pragma unroll
            for (int j = 0; j < 4; j++) s2[i][j] = 0ull;

#pragma unroll 2
        for (int d2 = 0; d2 < 32; d2++) {
            const int d = d2 << 1;
            ull q2[8], k2[4], e2[11];
#pragma unroll
            for (int il = 0; il < 8; il++)
                q2[il] = *(const ull*)&smf[qb + il * 68 + d];
#pragma unroll
            for (int ir = 0; ir < 4; ir++)
                k2[ir] = *(const ull*)&smf[kb + ir * 68 + d];
#pragma unroll
            for (int t = 0; t < 11; t++)
                e2[t] = *(const ull*)&smf[ebt[t] + d];
#pragma unroll
            for (int il = 0; il < 8; il++)
#pragma unroll
                for (int ir = 0; ir < 4; ir++) {
                    fma2(s2[il][ir], q2[il], k2[ir]);
                    fma2(s2[il][ir], q2[il], e2[il - ir + 3]);
                }
        }

        // ---- probs = exp(s/8 + am) * skim; store P; accumulate denoms
#pragma unroll
        for (int il = 0; il < 8; il++) {
            int l = ty * 8 + il;
            float rs = 0.f;
            float pr[4];
#pragma unroll
            for (int ir = 0; ir < 4; ir++) {
                float lo, hi;
                upk2(lo, hi, s2[il][ir]);
                float p = __expf((lo + hi) * 0.125f + smf[AMOFF + tx * 4 + ir])
                          * smf[SKOFF + tx * 4 + ir];
                pr[ir] = p;
                rs += p;
            }
            *(float2*)&smf[POFF + l * 66 + tx * 4]     = make_float2(pr[0], pr[1]);
            *(float2*)&smf[POFF + l * 66 + tx * 4 + 2] = make_float2(pr[2], pr[3]);
            rs += __shfl_xor_sync(0xffffffffu, rs, 1);
            rs += __shfl_xor_sync(0xffffffffu, rs, 2);
            rs += __shfl_xor_sync(0xffffffffu, rs, 4);
            rs += __shfl_xor_sync(0xffffffffu, rs, 8);
            if (tx == 0) smf[DNOFF + l] += rs;
        }
        __syncwarp();   // this warp's P rows (its own ty) fully written

        // ---- PV: rr-pairs; P pair loaded 64-bit, dup in registers
#pragma unroll 2
        for (int rr2 = 0; rr2 < 32; rr2++) {
            const int rr = rr2 << 1;
            ull v00 = *(const ull*)&smf[VOFF + rr * 68 + tx * 4];
            ull v01 = *(const ull*)&smf[VOFF + rr * 68 + tx * 4 + 2];
            ull v10 = *(const ull*)&smf[VOFF + (rr + 1) * 68 + tx * 4];
            ull v11 = *(const ull*)&smf[VOFF + (rr + 1) * 68 + tx * 4 + 2];
#pragma unroll
            for (int il = 0; il < 8; il++) {
                ull p2 = *(const ull*)&smf[POFF + (ty * 8 + il) * 66 + rr];
                float pa, pb;
                upk2(pa, pb, p2);
                ull pa2 = pk2(pa, pa);
                ull pb2 = pk2(pb, pb);
                fma2(pv2[il][0], pa2, v00);
                fma2(pv2[il][1], pa2, v01);
                fma2(pv2[il][0], pb2, v10);
                fma2(pv2[il][1], pb2, v11);
            }
        }
    }
    __syncthreads();

    // ---- write out: out[b, l, h*64 + d] = acc / (eps + denom)
#pragma unroll
    for (int il = 0; il < 8; il++) {
        int l = l0 + ty * 8 + il;
        float dinv = 1.f / (1e-8f + smf[DNOFF + ty * 8 + il]);
        float a0, a1, a2_, a3;
        upk2(a0, a1, pv2[il][0]);
        upk2(a2_, a3, pv2[il][1]);
        float4 o = make_float4(a0 * dinv, a1 * dinv, a2_ * dinv, a3 * dinv);
        *(float4*)&out[((size_t)(b * Sc + l)) * HIDc + h * 64 + tx * 4] = o;
    }
}

// ---------------------------------------------------------------------------
extern "C" void kernel_launch(void* const* d_in, const int* in_sizes, int n_in,
                              void* d_out, int out_size)
{
    const float* hidden = (const float*)d_in[0];
    const float* amask  = (const float*)d_in[1];
    const int*   skim   = (const int*)  d_in[2];
    const float* Wq     = (const float*)d_in[3];
    const float* bq     = (const float*)d_in[4];
    const float* Wk     = (const float*)d_in[5];
    const float* bk     = (const float*)d_in[6];
    const float* Wv     = (const float*)d_in[7];
    const float* bv     = (const float*)d_in[8];
    const float* demb   = (const float*)d_in[9];
    float* out = (float*)d_out;

    dim3 ggrid(8, 32);   // N/128, M/128
    gemm_proj<<<ggrid, 256>>>(hidden, Wq, bq, 0);
    gemm_proj<<<ggrid, 256>>>(hidden, Wk, bk, 1);
    gemm_proj<<<ggrid, 256>>>(hidden, Wv, bv, 2);

    cudaFuncSetAttribute(attn_kernel,
                         cudaFuncAttributeMaxDynamicSharedMemorySize,
                         ATTN_SMEM_BYTES);
    dim3 agrid(Sc / 64, Bc * Hc);
    attn_kernel<<<agrid, 128, ATTN_SMEM_BYTES>>>(amask, skim, demb, out);
}

// round 14
// speedup vs baseline: 1.6604x; 1.0234x over previous
#include <cuda_runtime.h>
#include <math.h>
#include <stdint.h>

// Problem constants
#define Bc   4
#define Sc   1024
#define HIDc 1024
#define Hc   16
#define Dc   64

// Scratch for Q, K, V in [B,H,S,D] layout (16 MB each)
__device__ float g_q[Bc * Hc * Sc * Dc];
__device__ float g_k[Bc * Hc * Sc * Dc];
__device__ float g_v[Bc * Hc * Sc * Dc];

typedef unsigned long long ull;

__device__ __forceinline__ ull pk2(float lo, float hi) {
    ull r;
    asm("mov.b64 %0, {%1, %2};" : "=l"(r) : "f"(lo), "f"(hi));
    return r;
}
__device__ __forceinline__ void upk2(float& lo, float& hi, ull v) {
    asm("mov.b64 {%0, %1}, %2;" : "=f"(lo), "=f"(hi) : "l"(v));
}
__device__ __forceinline__ void fma2(ull& d, ull a, ull b) {
    asm("fma.rn.f32x2 %0, %1, %2, %0;" : "+l"(d) : "l"(a), "l"(b));
}
__device__ __forceinline__ uint32_t smem_u32(const void* p) {
    uint32_t a;
    asm("{ .reg .u64 t; cvta.to.shared.u64 t, %1; cvt.u32.u64 %0, t; }"
        : "=r"(a) : "l"(p));
    return a;
}
__device__ __forceinline__ void cpa8(uint32_t dst, const void* src) {
    asm volatile("cp.async.ca.shared.global [%0], [%1], 8;"
                 :: "r"(dst), "l"(src) : "memory");
}
__device__ __forceinline__ void cpa16(uint32_t dst, const void* src) {
    asm volatile("cp.async.cg.shared.global [%0], [%1], 16;"
                 :: "r"(dst), "l"(src) : "memory");
}
#define CPA_COMMIT() asm volatile("cp.async.commit_group;" ::: "memory")
#define CPA_WAIT0()  asm volatile("cp.async.wait_group 0;" ::: "memory")

// ---------------------------------------------------------------------------
// Kernel A: projection GEMM  C = X @ W + bias, scattered to [B,H,S,D]
// (proven scalar version, ~660us for all three — at the FFMA roofline)
// ---------------------------------------------------------------------------
__global__ __launch_bounds__(256) void gemm_proj(const float* __restrict__ X,
                                                 const float* __restrict__ W,
                                                 const float* __restrict__ bias,
                                                 int which)
{
    __shared__ float As[16][132];
    __shared__ float Bs[16][132];
    float* outp = (which == 0) ? g_q : (which == 1) ? g_k : g_v;

    const int tid = threadIdx.x;
    const int m0  = blockIdx.y * 128;
    const int n0  = blockIdx.x * 128;
    const int ty  = tid >> 4;
    const int tx  = tid & 15;

    float acc[8][8];
#pragma unroll
    for (int i = 0; i < 8; i++)
#pragma unroll
        for (int j = 0; j < 8; j++) acc[i][j] = 0.f;

    for (int k0 = 0; k0 < 1024; k0 += 16) {
#pragma unroll
        for (int i = 0; i < 2; i++) {
            int f   = tid + i * 256;
            int row = f >> 2;
            int kc  = (f & 3) << 2;
            float4 va = *(const float4*)(X + (size_t)(m0 + row) * 1024 + k0 + kc);
            As[kc + 0][row] = va.x;
            As[kc + 1][row] = va.y;
            As[kc + 2][row] = va.z;
            As[kc + 3][row] = va.w;
        }
#pragma unroll
        for (int i = 0; i < 2; i++) {
            int f  = tid + i * 256;
            int kr = f >> 5;
            int nc = (f & 31) << 2;
            *(float4*)&Bs[kr][nc] =
                *(const float4*)(W + (size_t)(k0 + kr) * 1024 + n0 + nc);
        }
        __syncthreads();

#pragma unroll
        for (int kk = 0; kk < 16; kk++) {
            float a[8], b[8];
            *(float4*)&a[0] = *(const float4*)&As[kk][ty * 8];
            *(float4*)&a[4] = *(const float4*)&As[kk][ty * 8 + 4];
            *(float4*)&b[0] = *(const float4*)&Bs[kk][tx * 8];
            *(float4*)&b[4] = *(const float4*)&Bs[kk][tx * 8 + 4];
#pragma unroll
            for (int i = 0; i < 8; i++)
#pragma unroll
                for (int j = 0; j < 8; j++)
                    acc[i][j] += a[i] * b[j];
        }
        __syncthreads();
    }

#pragma unroll
    for (int i = 0; i < 8; i++) {
        int m = m0 + ty * 8 + i;
        int b = m >> 10;
        int s = m & 1023;
#pragma unroll
        for (int j = 0; j < 8; j++) {
            int n = n0 + tx * 8 + j;
            int h = n >> 6;
            int d = n & 63;
            outp[(((size_t)(b * Hc + h)) * Sc + s) * Dc + d] = acc[i][j] + bias[n];
        }
    }
}

// ---------------------------------------------------------------------------
// Kernel B: fused attention. 64x64 tiles, 8x4 micro-tile, 128 threads,
// f32x2 d-pair packed score FMAs, R13 bank rotations (unchanged),
// cp.async pipelining: K/E copied for next chunk during softmax+PV,
// V copied after PV; am/sk rows staged once in the prologue.
// ---------------------------------------------------------------------------
#define ROTK(r) ((((r) >> 2) & 15) << 1)
#define ROTE(r) ((((r) >> 2) & 31) << 1)

#define QOFF  0                     // 64 x 68                 = 4352
#define KOFF  4352                  // 64 x 68 + 32 rot        = 4384
#define VOFF  8736                  // 64 x 68                 = 4352
#define EOFF  13088                 // 127 x 68 + 64 rot       = 8700
#define POFF  21788                 // 64 x 66                 = 4224
#define DNOFF 26012                 // 64
#define AMOFF 26076                 // 1024 (full row)
#define SKOFF 27100                 // 1024 (full row, pre-converted)
#define SMEMF 28124
#define ATTN_SMEM_BYTES (SMEMF * 4) // 112496 B (2 CTAs/SM)

__global__ __launch_bounds__(128) void attn_kernel(const float* __restrict__ attn_mask,
                                                   const int*   __restrict__ skim,
                                                   const float* __restrict__ dist_emb,
                                                   float*       __restrict__ out)
{
    extern __shared__ float smf[];
    const uint32_t smb = smem_u32(smf);
    const int tid = threadIdx.x;
    const int l0  = blockIdx.x * 64;
    const int bh  = blockIdx.y;
    const int b   = bh >> 4;
    const int h   = bh & 15;
    const int ty  = tid >> 4;   // 0..7  -> 8 query rows each
    const int tx  = tid & 15;   // 0..15 -> 4 key cols each

    const float* q = g_q + (size_t)bh * Sc * Dc;
    const float* k = g_k + (size_t)bh * Sc * Dc;
    const float* v = g_v + (size_t)bh * Sc * Dc;

    // ---- async copy emitters (all 128 threads participate) ----
    auto issue_KE = [&](int r0n) {
        const float* ksrc = k + (size_t)r0n * 64;
#pragma unroll
        for (int i = 0; i < 16; i++) {       // K: 64 rows x 32 8B-units
            int u   = tid + i * 128;
            int row = u >> 5;
            int c2  = (u & 31) << 1;
            uint32_t dst = smb + (uint32_t)(KOFF + row * 68 + ROTK(row) + c2) * 4;
            cpa8(dst, ksrc + row * 64 + c2);
        }
        const float* esrc = dist_emb + (size_t)(l0 - r0n + 960) * 64;
#pragma unroll
        for (int i = 0; i < 32; i++) {       // E: 127 rows x 32 8B-units
            int u = tid + i * 128;
            if (u < 4064) {
                int row = u >> 5;
                int c2  = (u & 31) << 1;
                uint32_t dst = smb + (uint32_t)(EOFF + row * 68 + ROTE(row) + c2) * 4;
                cpa8(dst, esrc + (size_t)row * 64 + c2);
            }
        }
        CPA_COMMIT();
    };
    auto issue_V = [&](int r0n) {
        const float* vsrc = v + (size_t)r0n * 64;
#pragma unroll
        for (int i = 0; i < 8; i++) {        // V: 64 rows x 16 float4
            int u   = tid + i * 128;
            int row = u >> 4;
            int c4  = (u & 15) << 2;
            uint32_t dst = smb + (uint32_t)(VOFF + row * 68 + c4) * 4;
            cpa16(dst, vsrc + row * 64 + c4);
        }
        CPA_COMMIT();
    };

    // ---- prologue: Q tile, am/sk rows, chunk-0 K/E/V ----
    issue_KE(0);
    issue_V(0);
#pragma unroll
    for (int i = 0; i < 8; i++) {
        int f   = tid + i * 128;       // 0..1023 float4s
        int row = f >> 4;
        int c4  = (f & 15) << 2;
        float4 val = *(const float4*)(q + (size_t)(l0 + row) * 64 + c4);
        *(float4*)&smf[QOFF + row * 68 + c4] = val;
    }
#pragma unroll
    for (int i = 0; i < 8; i++) {
        int f = tid + i * 128;
        smf[AMOFF + f] = attn_mask[b * Sc + f];
        smf[SKOFF + f] = (float)skim[b * Sc + f];
    }
    if (tid < 64) smf[DNOFF + tid] = 0.f;
    CPA_WAIT0();
    __syncthreads();

    ull pv2[8][2];
#pragma unroll
    for (int i = 0; i < 8; i++) { pv2[i][0] = 0ull; pv2[i][1] = 0ull; }

    // Hoisted base addresses (chunk-invariant)
    const int jb0 = ty * 8 - tx * 4 + 60;      // in [0,116]
    int ebt[11];
#pragma unroll
    for (int t = 0; t < 11; t++) {
        int r = jb0 + t;                        // in [0,126]
        ebt[t] = EOFF + r * 68 + ROTE(r);
    }
    const int qb = QOFF + ty * 8 * 68;
    const int kb = KOFF + tx * 4 * 68 + (tx << 1);   // ROTK(4*tx) = 2*tx

    for (int c = 0; c < 16; c++) {
        // ---- Scores: s[il][ir] = sum_d q*(k) + q*(e), f32x2 over d-pairs
        ull s2[8][4];
#pragma unroll
        for (int i = 0; i < 8; i++)
#pragma unroll
            for (int j = 0; j < 4; j++) s2[i][j] = 0ull;

#pragma unroll 2
        for (int d2 = 0; d2 < 32; d2++) {
            const int d = d2 << 1;
            ull q2[8], k2[4], e2[11];
#pragma unroll
            for (int il = 0; il < 8; il++)
                q2[il] = *(const ull*)&smf[qb + il * 68 + d];
#pragma unroll
            for (int ir = 0; ir < 4; ir++)
                k2[ir] = *(const ull*)&smf[kb + ir * 68 + d];
#pragma unroll
            for (int t = 0; t < 11; t++)
                e2[t] = *(const ull*)&smf[ebt[t] + d];
#pragma unroll
            for (int il = 0; il < 8; il++)
#pragma unroll
                for (int ir = 0; ir < 4; ir++) {
                    fma2(s2[il][ir], q2[il], k2[ir]);
                    fma2(s2[il][ir], q2[il], e2[il - ir + 3]);
                }
        }
        __syncthreads();                 // all warps done reading K,E
        if (c < 15) issue_KE((c + 1) * 64);   // overlaps softmax + PV

        // ---- probs = exp(s/8 + am) * skim; store P; accumulate denoms
        const int amb = AMOFF + c * 64 + tx * 4;
        const int skb = SKOFF + c * 64 + tx * 4;
#pragma unroll
        for (int il = 0; il < 8; il++) {
            int l = ty * 8 + il;
            float rs = 0.f;
            float pr[4];
#pragma unroll
            for (int ir = 0; ir < 4; ir++) {
                float lo, hi;
                upk2(lo, hi, s2[il][ir]);
                float p = __expf((lo + hi) * 0.125f + smf[amb + ir]) * smf[skb + ir];
                pr[ir] = p;
                rs += p;
            }
            *(float2*)&smf[POFF + l * 66 + tx * 4]     = make_float2(pr[0], pr[1]);
            *(float2*)&smf[POFF + l * 66 + tx * 4 + 2] = make_float2(pr[2], pr[3]);
            rs += __shfl_xor_sync(0xffffffffu, rs, 1);
            rs += __shfl_xor_sync(0xffffffffu, rs, 2);
            rs += __shfl_xor_sync(0xffffffffu, rs, 4);
            rs += __shfl_xor_sync(0xffffffffu, rs, 8);
            if (tx == 0) smf[DNOFF + l] += rs;
        }
        __syncwarp();   // this warp's P rows (its own ty) fully written

        // ---- PV: rr-pairs; P pair loaded 64-bit, dup in registers
#pragma unroll 2
        for (int rr2 = 0; rr2 < 32; rr2++) {
            const int rr = rr2 << 1;
            ull v00 = *(const ull*)&smf[VOFF + rr * 68 + tx * 4];
            ull v01 = *(const ull*)&smf[VOFF + rr * 68 + tx * 4 + 2];
            ull v10 = *(const ull*)&smf[VOFF + (rr + 1) * 68 + tx * 4];
            ull v11 = *(const ull*)&smf[VOFF + (rr + 1) * 68 + tx * 4 + 2];
#pragma unroll
            for (int il = 0; il < 8; il++) {
                ull p2 = *(const ull*)&smf[POFF + (ty * 8 + il) * 66 + rr];
                float pa, pb;
                upk2(pa, pb, p2);
                ull pa2 = pk2(pa, pa);
                ull pb2 = pk2(pb, pb);
                fma2(pv2[il][0], pa2, v00);
                fma2(pv2[il][1], pa2, v01);
                fma2(pv2[il][0], pb2, v10);
                fma2(pv2[il][1], pb2, v11);
            }
        }
        __syncthreads();                 // all warps done reading V (and P)
        if (c < 15) issue_V((c + 1) * 64);
        CPA_WAIT0();                     // K',E',V' landed
        __syncthreads();
    }

    // ---- write out: out[b, l, h*64 + d] = acc / (eps + denom)
#pragma unroll
    for (int il = 0; il < 8; il++) {
        int l = l0 + ty * 8 + il;
        float dinv = 1.f / (1e-8f + smf[DNOFF + ty * 8 + il]);
        float a0, a1, a2_, a3;
        upk2(a0, a1, pv2[il][0]);
        upk2(a2_, a3, pv2[il][1]);
        float4 o = make_float4(a0 * dinv, a1 * dinv, a2_ * dinv, a3 * dinv);
        *(float4*)&out[((size_t)(b * Sc + l)) * HIDc + h * 64 + tx * 4] = o;
    }
}

// ---------------------------------------------------------------------------
extern "C" void kernel_launch(void* const* d_in, const int* in_sizes, int n_in,
                              void* d_out, int out_size)
{
    const float* hidden = (const float*)d_in[0];
    const float* amask  = (const float*)d_in[1];
    const int*   skim   = (const int*)  d_in[2];
    const float* Wq     = (const float*)d_in[3];
    const float* bq     = (const float*)d_in[4];
    const float* Wk     = (const float*)d_in[5];
    const float* bk     = (const float*)d_in[6];
    const float* Wv     = (const float*)d_in[7];
    const float* bv     = (const float*)d_in[8];
    const float* demb   = (const float*)d_in[9];
    float* out = (float*)d_out;

    dim3 ggrid(8, 32);   // N/128, M/128
    gemm_proj<<<ggrid, 256>>>(hidden, Wq, bq, 0);
    gemm_proj<<<ggrid, 256>>>(hidden, Wk, bk, 1);
    gemm_proj<<<ggrid, 256>>>(hidden, Wv, bv, 2);

    cudaFuncSetAttribute(attn_kernel,
                         cudaFuncAttributeMaxDynamicSharedMemorySize,
                         ATTN_SMEM_BYTES);
    dim3 agrid(Sc / 64, Bc * Hc);
    attn_kernel<<<agrid, 128, ATTN_SMEM_BYTES>>>(amask, skim, demb, out);
}